// round 3
// baseline (speedup 1.0000x reference)
#include <cuda_runtime.h>
#include <cuda_bf16.h>
#include <math.h>
#include <stdint.h>

#define B_ 8
#define N_ 4096
#define C_ 768
#define H_ 8
#define HD 96
#define M_ (B_*N_)        // 32768 rows
#define QKV_COLS (3*C_)   // 2304
#define KDIM 768
#define KSTAGES 24        // 768 / 32

// ---------------- scratch (device globals: allocation-free) ----------------
__device__ float g_qkv[(size_t)M_ * QKV_COLS];   // [M, 3C]
__device__ float g_ctx[(size_t)M_ * C_];         // [M, C]
__device__ float g_S[B_ * H_ * HD * HD];         // logits/attn
__device__ float g_rn[B_ * 2 * C_];              // 1/max(||col||,eps)
__device__ __nv_bfloat16 g_Bpk1[(size_t)18 * KSTAGES * 8192];  // Wqkv hi/lo
__device__ __nv_bfloat16 g_Bpk2[(size_t)6  * KSTAGES * 8192];  // Wproj hi/lo

// ---------------- PTX helpers ----------------------------------------------
__device__ __forceinline__ uint32_t smem_u32(const void* p) {
    uint32_t a;
    asm("{ .reg .u64 t; cvta.to.shared.u64 t, %1; cvt.u32.u64 %0, t; }" : "=r"(a) : "l"(p));
    return a;
}

#define LDSM4(r0, r1, r2, r3, addr) \
    asm volatile("ldmatrix.sync.aligned.m8n8.x4.shared.b16 {%0,%1,%2,%3}, [%4];" \
                 : "=r"(r0), "=r"(r1), "=r"(r2), "=r"(r3) : "r"(addr))

#define MMA16816(c, a, b0, b1) \
    asm volatile("mma.sync.aligned.m16n8k16.row.col.f32.bf16.bf16.f32 " \
                 "{%0,%1,%2,%3}, {%4,%5,%6,%7}, {%8,%9}, {%0,%1,%2,%3};" \
                 : "+f"((c)[0]), "+f"((c)[1]), "+f"((c)[2]), "+f"((c)[3]) \
                 : "r"((a)[0]), "r"((a)[1]), "r"((a)[2]), "r"((a)[3]), \
                   "r"(b0), "r"(b1))

#define CP_ASYNC16(dst, src) \
    asm volatile("cp.async.cg.shared.global [%0], [%1], 16;" \
                 :: "r"(dst), "l"(src) : "memory")
#define CP_COMMIT() asm volatile("cp.async.commit_group;" ::: "memory")
#define CP_WAIT1()  asm volatile("cp.async.wait_group 1;" ::: "memory")

// ---------------- weight prepack: W[K,N] -> bf16 hi/lo [n][k] tiles --------
// per (ntile, kstage) block of 8192 bf16: [hi 128x32][lo 128x32]
__global__ void prepack_kernel(const float* __restrict__ W,
                               __nv_bfloat16* __restrict__ pack, int Ncols)
{
    int id = blockIdx.x * 256 + threadIdx.x;
    int n = id % Ncols, k = id / Ncols;
    float w = W[id];
    __nv_bfloat16 h = __float2bfloat16_rn(w);
    __nv_bfloat16 lo = __float2bfloat16_rn(w - __bfloat162float(h));
    int nt = n >> 7, nl = n & 127, st = k >> 5, kl = k & 31;
    size_t base = ((size_t)nt * KSTAGES + st) * 8192 + (size_t)nl * 32 + kl;
    pack[base] = h;
    pack[base + 4096] = lo;
}

// ---------------- bf16 split-3 GEMM: 128x128x32 tile, mma.sync -------------
// SMEM per buffer (40960B, pitch 80): Ahi@0 Alo@10240 Bhi@20480 Blo@30720
#define BUF_BYTES 40960
#define GEMM_DSMEM (2 * BUF_BYTES + 128)

template<bool A_CTX, bool C_QKV>
__global__ void __launch_bounds__(256, 2)
gemm_bf16_kernel(const float* __restrict__ Ap, const __nv_bfloat16* __restrict__ Bpack,
                 float* __restrict__ Cp, const float* __restrict__ bias, int ldc)
{
    const float* A = A_CTX ? (const float*)g_ctx : Ap;
    float*       C = C_QKV ? (float*)g_qkv : Cp;

    extern __shared__ char dsm[];
    const int tid = threadIdx.x, wid = tid >> 5, lane = tid & 31;
    const int wm = wid >> 2, wn = wid & 3;          // 2 x 4 warp grid
    const int m0 = blockIdx.y * 128, bx = blockIdx.x;

    uint32_t dyn0 = smem_u32(dsm);
    uint32_t tile0 = (dyn0 + 127) & ~127u;

    // ldmatrix per-lane addressing
    const uint32_t ld_row = lane & 15;
    const uint32_t ld_k8b = ((lane >> 4) * 8) * 2;  // byte offset of k half
    const uint32_t a_off = (wm * 64 + ld_row) * 80 + ld_k8b;
    const uint32_t b_off = (wn * 32 + ld_row) * 80 + ld_k8b;

    float c[4][4][4];
#pragma unroll
    for (int i = 0; i < 4; i++)
#pragma unroll
        for (int j = 0; j < 4; j++)
#pragma unroll
            for (int q = 0; q < 4; q++) c[i][j][q] = 0.f;

    float4 ra[4];

    const char* bsrc_base = (const char*)Bpack + (size_t)bx * KSTAGES * 16384;
    // per-thread cp.async chunk coords (4 chunks of 16B = 64B/thread)
    // fid in [0,1024): half = fid>>9, row = (fid&511)>>2, cc = fid&3
    auto cp_stage = [&](int st, uint32_t bufb) {
        const char* src = bsrc_base + (size_t)st * 16384;
#pragma unroll
        for (int l = 0; l < 4; l++) {
            int fid = tid + 256 * l;
            int half = fid >> 9, rem = fid & 511, row = rem >> 2, cc = rem & 3;
            uint32_t dst = tile0 + bufb + 20480 + half * 10240 + row * 80 + cc * 16;
            CP_ASYNC16(dst, src + half * 8192 + row * 64 + cc * 16);
        }
    };
    auto ldg_stage = [&](int st) {
#pragma unroll
        for (int l = 0; l < 4; l++) {
            int fid = tid + 256 * l, r = fid >> 3, kc = fid & 7;
            ra[l] = *(const float4*)(A + (size_t)(m0 + r) * KDIM + st * 32 + kc * 4);
        }
    };
    auto sts_stage = [&](uint32_t bufb) {
        char* base = dsm + (tile0 - dyn0) + bufb;
#pragma unroll
        for (int l = 0; l < 4; l++) {
            int fid = tid + 256 * l, r = fid >> 3, kc = fid & 7;
            float4 a = ra[l];
            __nv_bfloat16 hx = __float2bfloat16_rn(a.x);
            __nv_bfloat16 hy = __float2bfloat16_rn(a.y);
            __nv_bfloat16 hz = __float2bfloat16_rn(a.z);
            __nv_bfloat16 hw = __float2bfloat16_rn(a.w);
            __nv_bfloat162 hi0; hi0.x = hx; hi0.y = hy;
            __nv_bfloat162 hi1; hi1.x = hz; hi1.y = hw;
            __nv_bfloat162 lo0, lo1;
            lo0.x = __float2bfloat16_rn(a.x - __bfloat162float(hx));
            lo0.y = __float2bfloat16_rn(a.y - __bfloat162float(hy));
            lo1.x = __float2bfloat16_rn(a.z - __bfloat162float(hz));
            lo1.y = __float2bfloat16_rn(a.w - __bfloat162float(hw));
            char* p = base + r * 80 + kc * 8;
            *(__nv_bfloat162*)(p)      = hi0;
            *(__nv_bfloat162*)(p + 4)  = hi1;
            *(__nv_bfloat162*)(p + 10240)     = lo0;
            *(__nv_bfloat162*)(p + 10240 + 4) = lo1;
        }
    };

    // prologue
    cp_stage(0, 0); CP_COMMIT();
    ldg_stage(0);

    for (int st = 0; st < KSTAGES; st++) {
        const uint32_t bufb = (st & 1) * BUF_BYTES;
        sts_stage(bufb);
        if (st + 1 < KSTAGES) cp_stage(st + 1, BUF_BYTES - bufb);
        CP_COMMIT();
        if (st + 1 < KSTAGES) ldg_stage(st + 1);
        CP_WAIT1();
        __syncthreads();

        // compute on bufb
        const uint32_t aP = tile0 + bufb;
        const uint32_t bP = aP + 20480;
        uint32_t af[4][4], bh[8], bl[8];
#pragma unroll
        for (int ks = 0; ks < 2; ks++) {
            const uint32_t ko = ks * 32;             // 16 k * 2B
            // A hi frags
#pragma unroll
            for (int mt = 0; mt < 4; mt++)
                LDSM4(af[mt][0], af[mt][1], af[mt][2], af[mt][3],
                      aP + a_off + mt * 1280 + ko);
            // B hi frags (n 0-15, n 16-31)
            LDSM4(bh[0], bh[1], bh[2], bh[3], bP + b_off + ko);
            LDSM4(bh[4], bh[5], bh[6], bh[7], bP + b_off + 1280 + ko);
#pragma unroll
            for (int mt = 0; mt < 4; mt++) {
                MMA16816(c[mt][0], af[mt], bh[0], bh[2]);
                MMA16816(c[mt][1], af[mt], bh[1], bh[3]);
                MMA16816(c[mt][2], af[mt], bh[4], bh[6]);
                MMA16816(c[mt][3], af[mt], bh[5], bh[7]);
            }
            // B lo frags
            LDSM4(bl[0], bl[1], bl[2], bl[3], bP + 10240 + b_off + ko);
            LDSM4(bl[4], bl[5], bl[6], bl[7], bP + 10240 + b_off + 1280 + ko);
#pragma unroll
            for (int mt = 0; mt < 4; mt++) {
                MMA16816(c[mt][0], af[mt], bl[0], bl[2]);
                MMA16816(c[mt][1], af[mt], bl[1], bl[3]);
                MMA16816(c[mt][2], af[mt], bl[4], bl[6]);
                MMA16816(c[mt][3], af[mt], bl[5], bl[7]);
            }
            // A lo frags (reuse af)
#pragma unroll
            for (int mt = 0; mt < 4; mt++)
                LDSM4(af[mt][0], af[mt][1], af[mt][2], af[mt][3],
                      aP + 10240 + a_off + mt * 1280 + ko);
#pragma unroll
            for (int mt = 0; mt < 4; mt++) {
                MMA16816(c[mt][0], af[mt], bh[0], bh[2]);
                MMA16816(c[mt][1], af[mt], bh[1], bh[3]);
                MMA16816(c[mt][2], af[mt], bh[4], bh[6]);
                MMA16816(c[mt][3], af[mt], bh[5], bh[7]);
            }
        }
        __syncthreads();
    }

    // epilogue
    const int g = lane >> 2, tg = lane & 3;
#pragma unroll
    for (int mt = 0; mt < 4; mt++) {
        const int r0 = m0 + wm * 64 + mt * 16 + g;
#pragma unroll
        for (int nb = 0; nb < 4; nb++) {
            const int col = bx * 128 + wn * 32 + nb * 8 + tg * 2;
            float bx0 = 0.f, bx1 = 0.f;
            if (bias) { bx0 = bias[col]; bx1 = bias[col + 1]; }
            *(float2*)(C + (size_t)r0 * ldc + col) =
                make_float2(c[mt][nb][0] + bx0, c[mt][nb][1] + bx1);
            *(float2*)(C + (size_t)(r0 + 8) * ldc + col) =
                make_float2(c[mt][nb][2] + bx0, c[mt][nb][3] + bx1);
        }
    }
}

// ---------------- column L2-norm reciprocals over token dim N --------------
__global__ void colnorm_kernel()
{
    const int b = blockIdx.y;
    const int lane = threadIdx.x & 31;
    const int w = threadIdx.x >> 5;
    const int j = blockIdx.x * 32 + lane;
    const float* p = g_qkv + (size_t)b * N_ * QKV_COLS + j;

    float s0 = 0.f, s1 = 0.f, s2 = 0.f, s3 = 0.f;
    for (int n0 = w * 4; n0 < N_; n0 += 32) {
        float v0 = p[(size_t)(n0 + 0) * QKV_COLS];
        float v1 = p[(size_t)(n0 + 1) * QKV_COLS];
        float v2 = p[(size_t)(n0 + 2) * QKV_COLS];
        float v3 = p[(size_t)(n0 + 3) * QKV_COLS];
        s0 += v0 * v0; s1 += v1 * v1; s2 += v2 * v2; s3 += v3 * v3;
    }
    __shared__ float red[8][32];
    red[w][lane] = (s0 + s1) + (s2 + s3);
    __syncthreads();
    if (w == 0) {
        float t = 0.f;
#pragma unroll
        for (int r = 0; r < 8; r++) t += red[r][lane];
        g_rn[b * (2 * C_) + j] = 1.f / fmaxf(sqrtf(t), 1e-12f);
    }
}

__global__ void zeroS_kernel()
{
    int i = blockIdx.x * blockDim.x + threadIdx.x;
    if (i < B_ * H_ * HD * HD) g_S[i] = 0.f;
}

// ---------------- QK^T partial: per (b,h), split N into 8 chunks -----------
__global__ void __launch_bounds__(256)
attn_partial_kernel()
{
    const int bh = blockIdx.x, b = bh >> 3, h = bh & 7;
    const int chunk = blockIdx.y;
    const int tid = threadIdx.x;
    const int te = tid & 15, td = tid >> 4;

    __shared__ float qs[32][96];
    __shared__ float ks[32][96];

    float acc[6][6];
#pragma unroll
    for (int i = 0; i < 6; i++)
#pragma unroll
        for (int j = 0; j < 6; j++) acc[i][j] = 0.f;

    const size_t base = ((size_t)(b * N_ + chunk * 512)) * QKV_COLS + h * HD;
    for (int t = 0; t < 16; t++) {
#pragma unroll
        for (int l = 0; l < 3; l++) {
            int fid = tid + l * 256;
            int r = fid / 24, cc = fid % 24;
            size_t off = base + (size_t)(t * 32 + r) * QKV_COLS + cc * 4;
            *(float4*)&qs[r][cc * 4] = *(const float4*)(g_qkv + off);
            *(float4*)&ks[r][cc * 4] = *(const float4*)(g_qkv + off + C_);
        }
        __syncthreads();
#pragma unroll 4
        for (int r = 0; r < 32; r++) {
            float a[6], bb[6];
#pragma unroll
            for (int i = 0; i < 6; i++) a[i] = qs[r][td * 6 + i];
#pragma unroll
            for (int j = 0; j < 6; j++) bb[j] = ks[r][te * 6 + j];
#pragma unroll
            for (int i = 0; i < 6; i++)
#pragma unroll
                for (int j = 0; j < 6; j++) acc[i][j] = fmaf(a[i], bb[j], acc[i][j]);
        }
        __syncthreads();
    }
    float* Sp = g_S + (size_t)bh * HD * HD;
#pragma unroll
    for (int i = 0; i < 6; i++)
#pragma unroll
        for (int j = 0; j < 6; j++)
            atomicAdd(&Sp[(td * 6 + i) * HD + te * 6 + j], acc[i][j]);
}

// ---------------- scale by 1/(||q|| ||k||) * temperature, softmax ----------
__global__ void softmax_kernel(const float* __restrict__ temp)
{
    const int bh = blockIdx.x, b = bh >> 3, h = bh & 7;
    const int d = threadIdx.x;
    if (d >= HD) return;
    float* row = g_S + (size_t)bh * HD * HD + d * HD;
    const float rq = g_rn[b * (2 * C_) + h * HD + d] * temp[h];
    const float* rk = g_rn + b * (2 * C_) + C_ + h * HD;

    float vals[HD];
    float m = -1e30f;
    for (int e = 0; e < HD; e++) {
        float v = row[e] * rq * rk[e];
        vals[e] = v;
        if (v > m) m = v;
    }
    float ssum = 0.f;
    for (int e = 0; e < HD; e++) {
        float v = expf(vals[e] - m);
        vals[e] = v;
        ssum += v;
    }
    float inv = 1.f / ssum;
    for (int e = 0; e < HD; e++) row[e] = vals[e] * inv;
}

// ---------------- AV: per (b,h) per 128-token block -------------------------
__global__ void __launch_bounds__(256)
av_kernel()
{
    const int nb = blockIdx.x;
    const int bh = blockIdx.y, b = bh >> 3, h = bh & 7;
    const int tid = threadIdx.x;
    const int tdd = tid & 15, tnn = tid >> 4;

    __shared__ float at[96][100];
    __shared__ float vs[16][132];

    const float* Sp = g_S + (size_t)bh * HD * HD;
#pragma unroll
    for (int l = 0; l < 36; l++) {
        int idx = tid + l * 256;
        int d = idx / 96, e = idx % 96;
        at[e][d] = Sp[idx];
    }

    float acc[8][6];
#pragma unroll
    for (int i = 0; i < 8; i++)
#pragma unroll
        for (int j = 0; j < 6; j++) acc[i][j] = 0.f;

    const size_t basev = ((size_t)(b * N_ + nb * 128)) * QKV_COLS + 2 * C_ + h * HD;
    for (int ec = 0; ec < 6; ec++) {
        __syncthreads();
#pragma unroll
        for (int l = 0; l < 2; l++) {
            int fid = tid + l * 256;
            int r = fid >> 2, cc = fid & 3;
            float4 v = *(const float4*)(g_qkv + basev + (size_t)r * QKV_COLS + ec * 16 + cc * 4);
            vs[cc * 4 + 0][r] = v.x; vs[cc * 4 + 1][r] = v.y;
            vs[cc * 4 + 2][r] = v.z; vs[cc * 4 + 3][r] = v.w;
        }
        __syncthreads();
#pragma unroll
        for (int e = 0; e < 16; e++) {
            float4 va = *(const float4*)&vs[e][tnn * 8];
            float4 vb = *(const float4*)&vs[e][tnn * 8 + 4];
            const float2* wp = (const float2*)&at[ec * 16 + e][tdd * 6];
            float2 w01 = wp[0], w23 = wp[1], w45 = wp[2];
            float a[8] = {va.x, va.y, va.z, va.w, vb.x, vb.y, vb.z, vb.w};
            float w[6] = {w01.x, w01.y, w23.x, w23.y, w45.x, w45.y};
#pragma unroll
            for (int i = 0; i < 8; i++)
#pragma unroll
                for (int j = 0; j < 6; j++) acc[i][j] = fmaf(a[i], w[j], acc[i][j]);
        }
    }

#pragma unroll
    for (int i = 0; i < 8; i++) {
        size_t row = (size_t)(b * N_ + nb * 128 + tnn * 8 + i);
        float* cp = g_ctx + row * C_ + h * HD + tdd * 6;
        *(float2*)(cp + 0) = make_float2(acc[i][0], acc[i][1]);
        *(float2*)(cp + 2) = make_float2(acc[i][2], acc[i][3]);
        *(float2*)(cp + 4) = make_float2(acc[i][4], acc[i][5]);
    }
}

// ---------------- launch ----------------------------------------------------
extern "C" void kernel_launch(void* const* d_in, const int* in_sizes, int n_in,
                              void* d_out, int out_size)
{
    const float* x     = (const float*)d_in[0];
    const float* Wqkv  = (const float*)d_in[1];
    const float* temp  = (const float*)d_in[2];
    const float* Wproj = (const float*)d_in[3];
    const float* bproj = (const float*)d_in[4];
    float* out = (float*)d_out;

    cudaFuncSetAttribute(gemm_bf16_kernel<false, true>,
                         cudaFuncAttributeMaxDynamicSharedMemorySize, GEMM_DSMEM);
    cudaFuncSetAttribute(gemm_bf16_kernel<true, false>,
                         cudaFuncAttributeMaxDynamicSharedMemorySize, GEMM_DSMEM);

    // 0) prepack weights (bf16 hi/lo split, [n][k] tiles)
    prepack_kernel<<<(KDIM * QKV_COLS) / 256, 256>>>(Wqkv, g_Bpk1, QKV_COLS);
    prepack_kernel<<<(KDIM * C_) / 256, 256>>>(Wproj, g_Bpk2, C_);

    // 1) qkv = x @ Wqkv  -> g_qkv [M, 3C]   (bf16 split-3 mma.sync)
    gemm_bf16_kernel<false, true><<<dim3(QKV_COLS / 128, M_ / 128), 256, GEMM_DSMEM>>>(
        x, g_Bpk1, nullptr, nullptr, QKV_COLS);

    // 2) per-(b,channel) reciprocal L2 norms of q and k columns
    colnorm_kernel<<<dim3((2 * C_) / 32, B_), 256>>>();

    // 3) zero logits, then QK^T partial sums
    zeroS_kernel<<<(B_ * H_ * HD * HD + 255) / 256, 256>>>();
    attn_partial_kernel<<<dim3(B_ * H_, 8), 256>>>();

    // 4) scale + softmax
    softmax_kernel<<<B_ * H_, 96>>>(temp);

    // 5) ctx = attn @ v
    av_kernel<<<dim3(32, B_ * H_), 256>>>();

    // 6) out = ctx @ Wproj + bproj   (bf16 split-3 mma.sync)
    gemm_bf16_kernel<true, false><<<dim3(C_ / 128, M_ / 128), 256, GEMM_DSMEM>>>(
        nullptr, g_Bpk2, out, bproj, C_);
}